// round 14
// baseline (speedup 1.0000x reference)
#include <cuda_runtime.h>
#include <math.h>

#define NN 8192

// One slot per row. 0 = empty. A half-CTA publishes ~bits(dot) via atomicCAS;
// the loser of the CAS receives the peer's dot in the returned old value.
// All communication stays in the L2 atomic domain: no fence, no acquire,
// no L1 invalidation -> g stays L1-resident for the streaming CTAs.
__device__ unsigned int g_slot[NN];

__device__ __forceinline__ float4 ldg_stream_noL1(const float4* p) {
    float4 r;
    asm("ld.global.nc.L1::no_allocate.v4.f32 {%0,%1,%2,%3}, [%4];"
        : "=f"(r.x), "=f"(r.y), "=f"(r.z), "=f"(r.w)
        : "l"(p));
    return r;
}

// Half-row streaming + last-arriver epilogue via value-carrying atomicCAS.
// grid = 16384 CTAs (2 per row), 256 threads, 4 front-batched 128-bit w-loads
// per thread (the R7 engine, ~7 TB/s standalone).
__global__ void __launch_bounds__(256, 8) izh_fused_kernel(
    const float* __restrict__ x_in,
    const float* __restrict__ v,
    const float* __restrict__ u,
    const float* __restrict__ g,
    const float* __restrict__ w,
    const float* __restrict__ a_p,
    const float* __restrict__ b_p,
    const float* __restrict__ c_p,
    const float* __restrict__ d_p,
    float* __restrict__ out)
{
    const int bid  = blockIdx.x;
    const int row  = bid >> 1;
    const int half = bid & 1;
    const int base = half * 1024;  // float4 units; a full row is 2048 float4

    const float4* __restrict__ wrow = reinterpret_cast<const float4*>(w + (size_t)row * NN);
    const float4* __restrict__ g4   = reinterpret_cast<const float4*>(g);

    float sum = 0.0f;
    #pragma unroll
    for (int i = 0; i < 4; ++i) {
        const int idx = base + threadIdx.x + i * 256;
        const float4 a = ldg_stream_noL1(&wrow[idx]);  // streaming, no L1 alloc
        const float4 b = __ldg(&g4[idx]);              // L1-resident
        sum += a.x * b.x;
        sum += a.y * b.y;
        sum += a.z * b.z;
        sum += a.w * b.w;
    }

    #pragma unroll
    for (int off = 16; off > 0; off >>= 1)
        sum += __shfl_xor_sync(0xffffffffu, sum, off);

    __shared__ float ssum[8];
    const int wid = threadIdx.x >> 5;
    if ((threadIdx.x & 31) == 0) ssum[wid] = sum;
    __syncthreads();

    if (threadIdx.x == 0) {
        float dot = 0.0f;
        #pragma unroll
        for (int i = 0; i < 8; ++i) dot += ssum[i];

        // Publish / rendezvous: CAS(slot, 0, ~bits(dot)).
        //  - success (old==0): we are first; peer will pick up our value.
        //  - failure: old == ~bits(peer_dot) -> we are second; run epilogue.
        // ~bits(dot) != 0 for any real dot (would require bits 0xFFFFFFFF,
        // a NaN payload no FP op produces).
        const unsigned int mybits = ~__float_as_uint(dot);
        const unsigned int old = atomicCAS(&g_slot[row], 0u, mybits);

        if (old != 0u) {
            const float other = __uint_as_float(~old);

            // float add commutative -> same result whichever half is second.
            const float I  = dot + other + __ldg(&x_in[row]);
            const float vv = __ldg(&v[row]);
            const float uu = __ldg(&u[row]);
            const float gg = __ldg(&g[row]);

            // Izhikevich quadratic dynamics
            const float v1 = vv + (0.04f * vv * vv + 5.0f * vv + 140.0f - uu + I);

            // differentiable spike surrogate: sigmoid(4 * (v1 - 30))
            const float s = 1.0f / (1.0f + expf(-4.0f * (v1 - 30.0f)));

            // hard spike mask for state resets
            const float spk = (v1 >= 30.0f) ? 1.0f : 0.0f;
            const float ns  = 1.0f - spk;

            const float du = fabsf(__ldg(&a_p[row])) * (fabsf(__ldg(&b_p[row])) * v1 - uu);
            const float dg = -gg / 6.5f;

            out[row]           = ns * v1 + spk * __ldg(&c_p[row]);        // v_out
            out[NN + row]      = s;                                        // spiked_s
            out[2 * NN + row]  = ns * (uu + du) + spk * __ldg(&d_p[row]);  // u_out
            out[3 * NN + row]  = ns * (gg + dg) + spk;                     // g_out

            // Reset slot to empty for the next launch / graph replay
            // (atomicExch keeps it in the L2 atomic domain; kernel boundary
            // guarantees visibility to the next replay).
            atomicExch(&g_slot[row], 0u);
        }
    }
}

extern "C" void kernel_launch(void* const* d_in, const int* in_sizes, int n_in,
                              void* d_out, int out_size)
{
    const float* x_in = (const float*)d_in[0];
    const float* v    = (const float*)d_in[1];
    const float* u    = (const float*)d_in[2];
    const float* g    = (const float*)d_in[3];
    const float* w    = (const float*)d_in[4];
    const float* a_p  = (const float*)d_in[5];
    const float* b_p  = (const float*)d_in[6];
    const float* c_p  = (const float*)d_in[7];
    const float* d_p  = (const float*)d_in[8];
    float* out = (float*)d_out;

    izh_fused_kernel<<<2 * NN, 256>>>(x_in, v, u, g, w, a_p, b_p, c_p, d_p, out);
}

// round 15
// speedup vs baseline: 1.0243x; 1.0243x over previous
#include <cuda_runtime.h>
#include <math.h>

#define NN 8192

// One rendezvous slot per row. 0 = empty. A half-CTA publishes ~bits(dot) via
// atomicCAS; the CAS loser receives the peer's dot in the returned old value.
// Pure L2-atomic communication: no fence, no acquire, no L1 invalidation.
__device__ unsigned int g_slot[NN];

__device__ __forceinline__ float4 ldg_stream_noL1(const float4* p) {
    float4 r;
    asm("ld.global.nc.L1::no_allocate.v4.f32 {%0,%1,%2,%3}, [%4];"
        : "=f"(r.x), "=f"(r.y), "=f"(r.z), "=f"(r.w)
        : "l"(p));
    return r;
}

// Half-row streaming + last-arriver epilogue via value-carrying atomicCAS.
// Epilogue scalars are prefetched at CTA START (thread 0, both halves), so the
// post-CAS tail is register-only: CAS -> FMA/MUFU chain -> 4 stores. This keeps
// CTA lifetime short and SM slots turning over for the streaming waves.
__global__ void __launch_bounds__(256, 8) izh_fused_kernel(
    const float* __restrict__ x_in,
    const float* __restrict__ v,
    const float* __restrict__ u,
    const float* __restrict__ g,
    const float* __restrict__ w,
    const float* __restrict__ a_p,
    const float* __restrict__ b_p,
    const float* __restrict__ c_p,
    const float* __restrict__ d_p,
    float* __restrict__ out)
{
    const int bid  = blockIdx.x;
    const int row  = bid >> 1;
    const int half = bid & 1;
    const int base = half * 1024;  // float4 units; a full row is 2048 float4

    const float4* __restrict__ wrow = reinterpret_cast<const float4*>(w + (size_t)row * NN);
    const float4* __restrict__ g4   = reinterpret_cast<const float4*>(g);

    // Prefetch epilogue scalars NOW (thread 0 of every half-CTA) — their DRAM
    // latency overlaps the w streaming below, so the post-CAS tail needs no loads.
    float pre_x = 0.f, pre_v = 0.f, pre_u = 0.f, pre_g = 0.f;
    float pre_a = 0.f, pre_b = 0.f, pre_c = 0.f, pre_d = 0.f;
    if (threadIdx.x == 0) {
        pre_x = __ldg(&x_in[row]);
        pre_v = __ldg(&v[row]);
        pre_u = __ldg(&u[row]);
        pre_g = __ldg(&g[row]);
        pre_a = __ldg(&a_p[row]);
        pre_b = __ldg(&b_p[row]);
        pre_c = __ldg(&c_p[row]);
        pre_d = __ldg(&d_p[row]);
    }

    float sum = 0.0f;
    #pragma unroll
    for (int i = 0; i < 4; ++i) {
        const int idx = base + threadIdx.x + i * 256;
        const float4 a = ldg_stream_noL1(&wrow[idx]);  // streaming, no L1 alloc
        const float4 b = __ldg(&g4[idx]);              // L1-resident
        sum += a.x * b.x;
        sum += a.y * b.y;
        sum += a.z * b.z;
        sum += a.w * b.w;
    }

    #pragma unroll
    for (int off = 16; off > 0; off >>= 1)
        sum += __shfl_xor_sync(0xffffffffu, sum, off);

    __shared__ float ssum[8];
    const int wid = threadIdx.x >> 5;
    if ((threadIdx.x & 31) == 0) ssum[wid] = sum;
    __syncthreads();

    if (threadIdx.x == 0) {
        float dot = 0.0f;
        #pragma unroll
        for (int i = 0; i < 8; ++i) dot += ssum[i];

        // Rendezvous: CAS(slot, 0, ~bits(dot)).
        //  - old==0: first arriver; peer will consume our value. Done.
        //  - old!=0: old == ~bits(peer_dot); run the register-only epilogue.
        // ~bits(dot) != 0 for any real dot (0 would require bits 0xFFFFFFFF,
        // a NaN payload no FP op produces).
        const unsigned int mybits = ~__float_as_uint(dot);
        const unsigned int old = atomicCAS(&g_slot[row], 0u, mybits);

        if (old != 0u) {
            const float other = __uint_as_float(~old);

            // float add commutative -> identical result either arrival order.
            const float I  = dot + other + pre_x;
            const float vv = pre_v;
            const float uu = pre_u;
            const float gg = pre_g;

            // Izhikevich quadratic dynamics
            const float v1 = vv + (0.04f * vv * vv + 5.0f * vv + 140.0f - uu + I);

            // differentiable spike surrogate: sigmoid(4 * (v1 - 30))
            const float s = 1.0f / (1.0f + expf(-4.0f * (v1 - 30.0f)));

            // hard spike mask for state resets
            const float spk = (v1 >= 30.0f) ? 1.0f : 0.0f;
            const float ns  = 1.0f - spk;

            const float du = fabsf(pre_a) * (fabsf(pre_b) * v1 - uu);
            const float dg = -gg / 6.5f;

            out[row]           = ns * v1 + spk * pre_c;           // v_out
            out[NN + row]      = s;                                // spiked_s
            out[2 * NN + row]  = ns * (uu + du) + spk * pre_d;     // u_out
            out[3 * NN + row]  = ns * (gg + dg) + spk;             // g_out

            // Reset slot for the next launch / graph replay (stays in the L2
            // atomic domain; fire-and-forget, no dependency).
            atomicExch(&g_slot[row], 0u);
        }
    }
}

extern "C" void kernel_launch(void* const* d_in, const int* in_sizes, int n_in,
                              void* d_out, int out_size)
{
    const float* x_in = (const float*)d_in[0];
    const float* v    = (const float*)d_in[1];
    const float* u    = (const float*)d_in[2];
    const float* g    = (const float*)d_in[3];
    const float* w    = (const float*)d_in[4];
    const float* a_p  = (const float*)d_in[5];
    const float* b_p  = (const float*)d_in[6];
    const float* c_p  = (const float*)d_in[7];
    const float* d_p  = (const float*)d_in[8];
    float* out = (float*)d_out;

    izh_fused_kernel<<<2 * NN, 256>>>(x_in, v, u, g, w, a_p, b_p, c_p, d_p, out);
}